// round 4
// baseline (speedup 1.0000x reference)
#include <cuda_runtime.h>
#include <cstdint>

#define T_STEPS 512

__device__ uint2    g_keys[T_STEPS];
__device__ unsigned g_spk[T_STEPS * 1024];     // [t][b*32 + word]
__device__ __align__(8) float g_w3t[400 * 120]; // transposed conv3 weights [k][o]

// ---------------- threefry2x32 (JAX), 20 rounds ----------------
__device__ __forceinline__ void threefry(unsigned k0, unsigned k1,
                                         unsigned x0, unsigned x1,
                                         unsigned &o0, unsigned &o1)
{
    unsigned k2 = k0 ^ k1 ^ 0x1BD11BDAu;
    x0 += k0; x1 += k1;
#define TF_R(r) { x0 += x1; x1 = __funnelshift_l(x1, x1, (r)); x1 ^= x0; }
    TF_R(13) TF_R(15) TF_R(26) TF_R(6)
    x0 += k1; x1 += k2 + 1u;
    TF_R(17) TF_R(29) TF_R(16) TF_R(24)
    x0 += k2; x1 += k0 + 2u;
    TF_R(13) TF_R(15) TF_R(26) TF_R(6)
    x0 += k0; x1 += k1 + 3u;
    TF_R(17) TF_R(29) TF_R(16) TF_R(24)
    x0 += k1; x1 += k2 + 4u;
    TF_R(13) TF_R(15) TF_R(26) TF_R(6)
    x0 += k2; x1 += k0 + 5u;
#undef TF_R
    o0 = x0; o1 = x1;
}

__global__ void keys_kernel()
{
    int t = threadIdx.x;
    if (t < T_STEPS) {
        unsigned a, b;
        threefry(0u, 1u, 0u, (unsigned)t, a, b);
        g_keys[t] = make_uint2(a, b);
    }
}

__global__ void __launch_bounds__(256) spikes_kernel(const float* __restrict__ image)
{
    unsigned gid = blockIdx.x * 256u + threadIdx.x;
    unsigned t = gid >> 15;
    unsigned i = gid & 32767u;
    uint2 k = g_keys[t];
    unsigned o0, o1;
    threefry(k.x, k.y, 0u, i, o0, o1);
    unsigned bits = o0 ^ o1;
    float u = __uint_as_float(0x3f800000u | (bits >> 9)) - 1.0f;
    float r = __ldg(image + i) * 0.1953125f;
    unsigned word = __ballot_sync(0xffffffffu, r > u);
    if ((threadIdx.x & 31u) == 0u)
        g_spk[t * 1024u + (i >> 5)] = word;
}

__global__ void __launch_bounds__(256) w3t_kernel(const float* __restrict__ w3)
{
    int i = blockIdx.x * 256 + threadIdx.x;   // 48000
    if (i < 48000) {
        int k = i / 120, o = i % 120;
        g_w3t[i] = w3[o * 400 + k];
    }
}

// ---------------- packed f32x2 helpers ----------------
typedef unsigned long long u64;

__device__ __forceinline__ void fma2(u64 &acc, u64 w, u64 p)
{
    asm("fma.rn.f32x2 %0, %1, %2, %3;" : "=l"(acc) : "l"(w), "l"(p), "l"(acc));
}
__device__ __forceinline__ void add2(u64 &acc, u64 p)
{
    asm("add.rn.f32x2 %0, %1, %2;" : "=l"(acc) : "l"(p), "l"(acc));
}
__device__ __forceinline__ float2 u2f(u64 v)
{
    float2 r;
    asm("mov.b64 {%0, %1}, %2;" : "=f"(r.x), "=f"(r.y) : "l"(v));
    return r;
}

// ---------------- shared memory map (float offsets, all 8B-aligned bases) ----
#define SM_XF     0        // 1024
#define SM_XFO    1024     // 1024  XF shifted by +1 within each 32-row
#define SM_SKB    2048     // 1176
#define SM_SKBO   3224     // 1176  SKB shifted by +1 within each 14-row
#define SM_M12A   4400     // 9408
#define SM_M12C   13808    // 3200
#define SM_PARTB  17008    // 1600
#define SM_PARTC  18608    // 360
#define SM_SKE    18968    // 120
#define SM_M12F   19088    // 168
#define SM_SKF    19256    // 84
#define SM_M12G   19340    // 20
#define SM_ACC    19360    // 10
#define SM_WCNT   19370    // 13 ints
#define SM_LIST   19383    // 13*32 ints
#define SM_W1D    19800    // 300  (w1 duplicated pairs)
#define SM_W2D    20100    // 4800 (w2 duplicated pairs)
#define SM_FW1    24900    // 10080
#define SM_FW2    34980    // 840
#define SM_TOTAL  35820
#define SMEM_BYTES (SM_TOTAL * 4)
#define SM_ZBEG   SM_M12A
#define SM_ZEND   SM_WCNT

__global__ void __launch_bounds__(1024, 1)
sim_kernel(const float* __restrict__ w1, const float* __restrict__ w2,
           const float* __restrict__ fw1, const float* __restrict__ fw2,
           float* __restrict__ out)
{
    extern __shared__ float sm[];
    int* const wcnt  = (int*)(sm + SM_WCNT);
    int* const listi = (int*)(sm + SM_LIST);

    const int tid  = threadIdx.x;
    const int b    = blockIdx.x;
    const int lane = tid & 31;
    const int wrp  = tid >> 5;

    for (int i = tid; i < 150;  i += 1024) {
        float f = w1[i];
        sm[SM_W1D + 2 * i] = f; sm[SM_W1D + 2 * i + 1] = f;
    }
    for (int i = tid; i < 2400; i += 1024) {
        float f = w2[i];
        sm[SM_W2D + 2 * i] = f; sm[SM_W2D + 2 * i + 1] = f;
    }
    for (int i = tid; i < 10080; i += 1024) sm[SM_FW1 + i] = fw1[i];
    for (int i = tid; i < 840;   i += 1024) sm[SM_FW2 + i] = fw2[i];
    for (int i = tid; i < (SM_ZEND - SM_ZBEG); i += 1024) sm[SM_ZBEG + i] = 0.0f;

    const unsigned* spk_base = g_spk + b * 32;
    // preload XF / XFO for t=0
    {
        unsigned w = __ldg(spk_base + wrp);
        sm[SM_XF + tid]  = (float)((w >> lane) & 1u);
        sm[SM_XFO + tid] = (lane == 31) ? 0.f : (float)((w >> (lane + 1)) & 1u);
    }
    __syncthreads();

    // ---- static mappings ----
    const int a_c  = tid / 98;                 // A: tid<588
    const int a_r  = tid % 98;
    const int a_by = a_r / 7;
    const int a_p  = a_r % 7;
    const int b_oc = tid / 60;                 // B1: tid<960
    const int b_rm = tid % 60;
    const int b_ic = b_rm / 10;
    const int b_oy = b_rm % 10;
    const int c_sp = tid >> 7;                 // C1: tid<512, pairs o2<60
    const int c_o2 = tid & 127;
    const int d_g  = tid >> 3;                 // D: tid<672
    const int d_j  = tid & 7;

    // register-resident LIF state
    float pm1[2] = {0.f, 0.f}, pm2[2] = {0.f, 0.f};
    float qm1 = 0.f, qm2 = 0.f;
    float em1a = 0.f, em2a = 0.f, em1b = 0.f, em2b = 0.f;

#pragma unroll 1
    for (int t = 0; t < T_STEPS; t++) {
        // ---- A: conv1 (f32x2) + lif1 + pool + lif2 -> SKB/SKBO ----
        if (tid < 588) {
            const u64* wd = (const u64*)(sm + SM_W1D) + a_c * 25;
#pragma unroll
            for (int half = 0; half < 2; half++) {
                int px = 2 * a_p + half;
                int x0 = 2 * px;
                u64 accT = 0ull, accB = 0ull;
                u64 wp0 = 0, wp1 = 0, wp2 = 0, wp3 = 0, wp4 = 0;
#pragma unroll
                for (int r = 0; r < 6; r++) {
                    const float* re = sm + SM_XF  + (2 * a_by + r) * 32 + x0;
                    const float* ro = sm + SM_XFO + (2 * a_by + r) * 32 + x0;
                    u64 p0 = *(const u64*)(re);
                    u64 p1 = *(const u64*)(ro);
                    u64 p2 = *(const u64*)(re + 2);
                    u64 p3 = *(const u64*)(ro + 2);
                    u64 p4 = *(const u64*)(re + 4);
                    if (r > 0) {
                        fma2(accB, wp0, p0); fma2(accB, wp1, p1); fma2(accB, wp2, p2);
                        fma2(accB, wp3, p3); fma2(accB, wp4, p4);
                    }
                    if (r < 5) {
                        u64 w0 = wd[r*5+0], w1_ = wd[r*5+1], w2_ = wd[r*5+2],
                            w3_ = wd[r*5+3], w4_ = wd[r*5+4];
                        fma2(accT, w0, p0); fma2(accT, w1_, p1); fma2(accT, w2_, p2);
                        fma2(accT, w3_, p3); fma2(accT, w4_, p4);
                        wp0 = w0; wp1 = w1_; wp2 = w2_; wp3 = w3_; wp4 = w4_;
                    }
                }
                float2 vT = u2f(accT), vB = u2f(accB);
                float dr0[4] = {vT.x, vT.y, vB.x, vB.y};
                float psum = 0.f;
                int ob = a_c * 784 + (2 * a_by) * 28 + x0;
#pragma unroll
                for (int q = 0; q < 4; q++) {
                    int o = ob + (q >> 1) * 28 + (q & 1);
                    float2 m = *(float2*)(sm + SM_M12A + 2 * o);
                    float oms = (m.y > 0.3f) ? 0.f : 1.f;
                    float nm1 = m.x * 0.25f * oms + dr0[q];
                    float nm2 = m.y * 0.25f * oms + 0.5f * nm1;
                    *(float2*)(sm + SM_M12A + 2 * o) = make_float2(nm1, nm2);
                    psum += (nm2 > 0.3f) ? 1.f : 0.f;
                }
                float d   = 0.25f * psum;
                float oms = (pm2[half] > 0.3f) ? 0.f : 1.f;
                float nm1 = pm1[half] * 0.25f * oms + d;
                float nm2 = pm2[half] * 0.25f * oms + 0.5f * nm1;
                pm1[half] = nm1; pm2[half] = nm2;
                float sv = (nm2 > 0.3f) ? 1.f : 0.f;
                int si = a_c * 196 + a_by * 14 + px;
                sm[SM_SKB + si] = sv;
                if (px > 0) sm[SM_SKBO + si - 1] = sv;
            }
        }
        __syncthreads();

        // ---- B1: conv2 partials, thread=(oc,ic,oy), 10 outputs as 5 f32x2 ----
        if (tid < 960) {
            const u64* wd = (const u64*)(sm + SM_W2D) + (b_oc * 6 + b_ic) * 25;
            u64 A0 = 0, A1 = 0, A2 = 0, A3 = 0, A4 = 0;
#pragma unroll
            for (int r = 0; r < 5; r++) {
                const float* re = sm + SM_SKB  + b_ic * 196 + (b_oy + r) * 14;
                const float* ro = sm + SM_SKBO + b_ic * 196 + (b_oy + r) * 14;
                u64 p[13];
#pragma unroll
                for (int k = 0; k < 7; k++) p[2 * k] = *(const u64*)(re + 2 * k);
#pragma unroll
                for (int k = 0; k < 6; k++) p[2 * k + 1] = *(const u64*)(ro + 2 * k);
#pragma unroll
                for (int kx = 0; kx < 5; kx++) {
                    u64 w = wd[r * 5 + kx];
                    fma2(A0, w, p[kx]);
                    fma2(A1, w, p[2 + kx]);
                    fma2(A2, w, p[4 + kx]);
                    fma2(A3, w, p[6 + kx]);
                    fma2(A4, w, p[8 + kx]);
                }
            }
            u64* pp = (u64*)(sm + SM_PARTB + b_ic * 1600 + b_oc * 100 + b_oy * 10);
            pp[0] = A0; pp[1] = A1; pp[2] = A2; pp[3] = A3; pp[4] = A4;
        }
        __syncthreads();

        // ---- B2: reduce ic + lif3 + pool + lif4 + per-warp spike segments ----
        bool spiked = false;
        int myk = 0;
        if (tid < 400) {
            int oc = tid / 25, rem = tid % 25, py = rem / 5, pxx = rem % 5;
            u64 sT = 0, sB = 0;
#pragma unroll
            for (int ic = 0; ic < 6; ic++) {
                int ib = ic * 1600 + oc * 100;
                add2(sT, *(const u64*)(sm + SM_PARTB + ib + (2 * py) * 10 + 2 * pxx));
                add2(sB, *(const u64*)(sm + SM_PARTB + ib + (2 * py + 1) * 10 + 2 * pxx));
            }
            float2 vT = u2f(sT), vB = u2f(sB);
            float dr0[4] = {vT.x, vT.y, vB.x, vB.y};
            float psum = 0.f;
            int ob = oc * 100 + (2 * py) * 10 + 2 * pxx;
#pragma unroll
            for (int q = 0; q < 4; q++) {
                int o = ob + (q >> 1) * 10 + (q & 1);
                float2 m = *(float2*)(sm + SM_M12C + 2 * o);
                float oms = (m.y > 0.3f) ? 0.f : 1.f;
                float nm1 = m.x * 0.25f * oms + dr0[q];
                float nm2 = m.y * 0.25f * oms + 0.5f * nm1;
                *(float2*)(sm + SM_M12C + 2 * o) = make_float2(nm1, nm2);
                psum += (nm2 > 0.3f) ? 1.f : 0.f;
            }
            float d   = 0.25f * psum;
            float oms = (qm2 > 0.3f) ? 0.f : 1.f;
            float nm1 = qm1 * 0.25f * oms + d;
            float nm2 = qm2 * 0.25f * oms + 0.5f * nm1;
            qm1 = nm1; qm2 = nm2;
            if (nm2 > 0.3f) { spiked = true; myk = oc * 25 + rem; }
        }
        {
            unsigned bm = __ballot_sync(0xffffffffu, spiked);
            if (spiked) listi[wrp * 32 + __popc(bm & ((1u << lane) - 1u))] = myk;
            if (lane == 0 && wrp < 13) wcnt[wrp] = __popc(bm);
        }
        __syncthreads();

        // ---- C1: sparse conv3 gather (pairs), 4-way segment split ----
        u64 cacc = 0;
        if (tid < 512 && c_o2 < 60) {
            const u64* w3p = (const u64*)g_w3t;
            for (int w = c_sp; w < 13; w += 4) {
                int n = wcnt[w];
                const int* seg = listi + w * 32;
                for (int j = 0; j < n; j++) {
                    int k = seg[j];
                    add2(cacc, __ldg(w3p + k * 60 + c_o2));
                }
            }
            if (c_sp) *(u64*)(sm + SM_PARTC + (c_sp - 1) * 120 + 2 * c_o2) = cacc;
        }
        __syncthreads();

        // ---- C2: combine + lif5 -> SKE ----
        if (tid < 60) {
            add2(cacc, *(const u64*)(sm + SM_PARTC + 2 * tid));
            add2(cacc, *(const u64*)(sm + SM_PARTC + 120 + 2 * tid));
            add2(cacc, *(const u64*)(sm + SM_PARTC + 240 + 2 * tid));
            float2 v = u2f(cacc);
            float oms = (em2a > 0.3f) ? 0.f : 1.f;
            float n1  = em1a * 0.25f * oms + v.x;
            float n2  = em2a * 0.25f * oms + 0.5f * n1;
            em1a = n1; em2a = n2;
            sm[SM_SKE + 2 * tid] = (n2 > 0.3f) ? 1.f : 0.f;
            float omsb = (em2b > 0.3f) ? 0.f : 1.f;
            float n1b  = em1b * 0.25f * omsb + v.y;
            float n2b  = em2b * 0.25f * omsb + 0.5f * n1b;
            em1b = n1b; em2b = n2b;
            sm[SM_SKE + 2 * tid + 1] = (n2b > 0.3f) ? 1.f : 0.f;
        }
        __syncthreads();

        // ---- D: fc1 + lif6 -> SKF ----
        if (tid < 672) {
            const float* wp = sm + SM_FW1 + d_g * 120;
            float s = 0.f;
#pragma unroll
            for (int k = d_j; k < 120; k += 8) s = fmaf(wp[k], sm[SM_SKE + k], s);
            s += __shfl_xor_sync(0xffffffffu, s, 4);
            s += __shfl_xor_sync(0xffffffffu, s, 2);
            s += __shfl_xor_sync(0xffffffffu, s, 1);
            if (d_j == 0) {
                float2 m = *(float2*)(sm + SM_M12F + 2 * d_g);
                float oms = (m.y > 0.3f) ? 0.f : 1.f;
                float nm1 = m.x * 0.25f * oms + s;
                float nm2 = m.y * 0.25f * oms + 0.5f * nm1;
                *(float2*)(sm + SM_M12F + 2 * d_g) = make_float2(nm1, nm2);
                sm[SM_SKF + d_g] = (nm2 > 0.3f) ? 1.f : 0.f;
            }
        }
        __syncthreads();

        // ---- E: fc2 + lif7 + acc (warps 0-9) | XF(t+1) preload (warps 10+) ----
        if (wrp < 10) {
            const float* wp = sm + SM_FW2 + wrp * 84;
            float s = 0.f;
            for (int k = lane; k < 84; k += 32) s = fmaf(wp[k], sm[SM_SKF + k], s);
#pragma unroll
            for (int d2 = 16; d2 > 0; d2 >>= 1) s += __shfl_xor_sync(0xffffffffu, s, d2);
            if (lane == 0) {
                float2 m = *(float2*)(sm + SM_M12G + 2 * wrp);
                float oms = (m.y > 0.3f) ? 0.f : 1.f;
                float nm1 = m.x * 0.25f * oms + s;
                float nm2 = m.y * 0.25f * oms + 0.5f * nm1;
                *(float2*)(sm + SM_M12G + 2 * wrp) = make_float2(nm1, nm2);
                sm[SM_ACC + wrp] += (nm2 > 0.3f) ? 1.f : 0.f;
            }
        } else if (t + 1 < T_STEPS) {
            const unsigned* sb = spk_base + (unsigned)(t + 1) * 1024u;
            for (int i = tid - 320; i < 1024; i += 704) {
                unsigned w = __ldg(sb + (i >> 5));
                int l = i & 31;
                sm[SM_XF + i]  = (float)((w >> l) & 1u);
                sm[SM_XFO + i] = (l == 31) ? 0.f : (float)((w >> (l + 1)) & 1u);
            }
        }
        __syncthreads();
    }

    if (tid < 10)
        out[b * 10 + tid] = sm[SM_ACC + tid] * (1.0f / 512.0f);
}

extern "C" void kernel_launch(void* const* d_in, const int* in_sizes, int n_in,
                              void* d_out, int out_size)
{
    const float* image = (const float*)d_in[0];
    const float* w1    = (const float*)d_in[1];
    const float* w2    = (const float*)d_in[2];
    const float* w3    = (const float*)d_in[3];
    const float* fw1   = (const float*)d_in[4];
    const float* fw2   = (const float*)d_in[5];
    float* out = (float*)d_out;

    keys_kernel<<<1, 512>>>();
    spikes_kernel<<<(T_STEPS * 32768) / 256, 256>>>(image);
    w3t_kernel<<<(48000 + 255) / 256, 256>>>(w3);
    cudaFuncSetAttribute(sim_kernel, cudaFuncAttributeMaxDynamicSharedMemorySize, SMEM_BYTES);
    sim_kernel<<<32, 1024, SMEM_BYTES>>>(w1, w2, fw1, fw2, out);
}

// round 5
// speedup vs baseline: 1.7576x; 1.7576x over previous
#include <cuda_runtime.h>
#include <cstdint>

#define T_STEPS 512

__device__ uint2    g_keys[T_STEPS];
__device__ unsigned g_spk[T_STEPS * 1024];      // [t][b*32 + word]
__device__ __align__(8) float g_w3t[400 * 120]; // transposed conv3 weights [k][o]

// ---------------- threefry2x32 (JAX), 20 rounds ----------------
__device__ __forceinline__ void threefry(unsigned k0, unsigned k1,
                                         unsigned x0, unsigned x1,
                                         unsigned &o0, unsigned &o1)
{
    unsigned k2 = k0 ^ k1 ^ 0x1BD11BDAu;
    x0 += k0; x1 += k1;
#define TF_R(r) { x0 += x1; x1 = __funnelshift_l(x1, x1, (r)); x1 ^= x0; }
    TF_R(13) TF_R(15) TF_R(26) TF_R(6)
    x0 += k1; x1 += k2 + 1u;
    TF_R(17) TF_R(29) TF_R(16) TF_R(24)
    x0 += k2; x1 += k0 + 2u;
    TF_R(13) TF_R(15) TF_R(26) TF_R(6)
    x0 += k0; x1 += k1 + 3u;
    TF_R(17) TF_R(29) TF_R(16) TF_R(24)
    x0 += k1; x1 += k2 + 4u;
    TF_R(13) TF_R(15) TF_R(26) TF_R(6)
    x0 += k2; x1 += k0 + 5u;
#undef TF_R
    o0 = x0; o1 = x1;
}

__global__ void keys_kernel()
{
    int t = threadIdx.x;
    if (t < T_STEPS) {
        unsigned a, b;
        threefry(0u, 1u, 0u, (unsigned)t, a, b);
        g_keys[t] = make_uint2(a, b);
    }
}

__global__ void __launch_bounds__(256) spikes_kernel(const float* __restrict__ image)
{
    unsigned gid = blockIdx.x * 256u + threadIdx.x;
    unsigned t = gid >> 15;
    unsigned i = gid & 32767u;
    uint2 k = g_keys[t];
    unsigned o0, o1;
    threefry(k.x, k.y, 0u, i, o0, o1);
    unsigned bits = o0 ^ o1;
    float u = __uint_as_float(0x3f800000u | (bits >> 9)) - 1.0f;
    float r = __ldg(image + i) * 0.1953125f;
    unsigned word = __ballot_sync(0xffffffffu, r > u);
    if ((threadIdx.x & 31u) == 0u)
        g_spk[t * 1024u + (i >> 5)] = word;
}

__global__ void __launch_bounds__(256) w3t_kernel(const float* __restrict__ w3)
{
    int i = blockIdx.x * 256 + threadIdx.x;   // 48000
    if (i < 48000) {
        int k = i / 120, o = i % 120;
        g_w3t[i] = w3[o * 400 + k];
    }
}

typedef unsigned long long u64;
__device__ __forceinline__ void add2(u64 &acc, u64 p)
{
    asm("add.rn.f32x2 %0, %1, %2;" : "=l"(acc) : "l"(p), "l"(acc));
}
__device__ __forceinline__ float2 u2f(u64 v)
{
    float2 r;
    asm("mov.b64 {%0, %1}, %2;" : "=f"(r.x), "=f"(r.y) : "l"(v));
    return r;
}

// ---------------- shared memory map (float offsets) ----------------
#define SM_XF     0        // 1024
#define SM_SKB    1024     // 1176
#define SM_M12A   2200     // 9408
#define SM_M12C   11608    // 3200
#define SM_PARTB  14808    // 9600 = ic(6) x oc(16) x 10 x 10
#define SM_PARTC  24408    // 360
#define SM_SKE    24768    // 120
#define SM_M12F   24888    // 168
#define SM_SKF    25056    // 84
#define SM_M12G   25140    // 20
#define SM_ACC    25160    // 10
#define SM_WCNT   25170    // 13 ints
#define SM_LIST   25184    // 416 ints
#define SM_W1     25600    // 150
#define SM_W2     25752    // 2400
#define SM_FW1    28152    // 10080
#define SM_FW2    38232    // 840
#define SM_TOTAL  39072
#define SMEM_BYTES (SM_TOTAL * 4)
#define SM_ZBEG   SM_M12A
#define SM_ZEND   SM_W1

__global__ void __launch_bounds__(1024, 1)
sim_kernel(const float* __restrict__ w1, const float* __restrict__ w2,
           const float* __restrict__ fw1, const float* __restrict__ fw2,
           float* __restrict__ out)
{
    extern __shared__ float sm[];
    int* const wcnt  = (int*)(sm + SM_WCNT);
    int* const listi = (int*)(sm + SM_LIST);

    const int tid  = threadIdx.x;
    const int b    = blockIdx.x;
    const int lane = tid & 31;
    const int wrp  = tid >> 5;

    for (int i = tid; i < 150;   i += 1024) sm[SM_W1  + i] = w1[i];
    for (int i = tid; i < 2400;  i += 1024) sm[SM_W2  + i] = w2[i];
    for (int i = tid; i < 10080; i += 1024) sm[SM_FW1 + i] = fw1[i];
    for (int i = tid; i < 840;   i += 1024) sm[SM_FW2 + i] = fw2[i];
    for (int i = tid; i < (SM_ZEND - SM_ZBEG); i += 1024) sm[SM_ZBEG + i] = 0.0f;

    const unsigned* spk_base = g_spk + b * 32;
    {   // preload XF for t=0
        unsigned w = __ldg(spk_base + wrp);
        sm[SM_XF + tid] = (float)((w >> lane) & 1u);
    }
    __syncthreads();

    // ---- static mappings ----
    const int a_c  = tid / 98;                 // A: tid<588 (c, by, p)
    const int a_r  = tid % 98;
    const int a_by = a_r / 7;
    const int a_p  = a_r % 7;
    const int c2_oc  = tid / 30;               // B1: tid<480 (oc, ic, oy2)
    const int c2_rm  = tid % 30;
    const int c2_ic  = c2_rm / 5;
    const int c2_oy2 = c2_rm % 5;
    const int c_sp = tid >> 7;                 // C1: tid<512, o2<60
    const int c_o2 = tid & 127;
    const int d_g  = tid >> 3;                 // D: tid<672
    const int d_j  = tid & 7;

    // register-resident LIF state
    float pm1[2] = {0.f, 0.f}, pm2[2] = {0.f, 0.f};   // layer2 pooled
    float qm1 = 0.f, qm2 = 0.f;                        // layer4 pooled
    float em1a = 0.f, em2a = 0.f, em1b = 0.f, em2b = 0.f; // layer5

#pragma unroll 1
    for (int t = 0; t < T_STEPS; t++) {
        // ---- A: conv1 (2x4 block, rolling rows) + lif1 + pool + lif2 ----
        if (tid < 588) {
            const float* wr = sm + SM_W1 + a_c * 25;
            float acc[8];
#pragma unroll
            for (int q = 0; q < 8; q++) acc[q] = 0.f;
#pragma unroll
            for (int r = 0; r < 6; r++) {
                const float* row = sm + SM_XF + (2 * a_by + r) * 32 + 4 * a_p;
                float4 v0 = *(const float4*)row;
                float4 v1 = *(const float4*)(row + 4);
                float in[8] = {v0.x, v0.y, v0.z, v0.w, v1.x, v1.y, v1.z, v1.w};
                if (r < 5) {
#pragma unroll
                    for (int kx = 0; kx < 5; kx++) {
                        float wv = wr[r * 5 + kx];
#pragma unroll
                        for (int j = 0; j < 4; j++)
                            acc[j] = fmaf(wv, in[kx + j], acc[j]);
                    }
                }
                if (r >= 1) {
#pragma unroll
                    for (int kx = 0; kx < 5; kx++) {
                        float wv = wr[(r - 1) * 5 + kx];
#pragma unroll
                        for (int j = 0; j < 4; j++)
                            acc[4 + j] = fmaf(wv, in[kx + j], acc[4 + j]);
                    }
                }
            }
            int ob = a_c * 784 + (2 * a_by) * 28 + 4 * a_p;
            float ps[2] = {0.f, 0.f};
#pragma unroll
            for (int q = 0; q < 8; q++) {
                int oy = q >> 2, j = q & 3;
                int o = ob + oy * 28 + j;
                float2 m = *(float2*)(sm + SM_M12A + 2 * o);
                float oms = (m.y > 0.3f) ? 0.f : 1.f;
                float n1 = m.x * 0.25f * oms + acc[q];
                float n2 = m.y * 0.25f * oms + 0.5f * n1;
                *(float2*)(sm + SM_M12A + 2 * o) = make_float2(n1, n2);
                ps[j >> 1] += (n2 > 0.3f) ? 1.f : 0.f;
            }
#pragma unroll
            for (int h = 0; h < 2; h++) {
                float d   = 0.25f * ps[h];
                float oms = (pm2[h] > 0.3f) ? 0.f : 1.f;
                float n1  = pm1[h] * 0.25f * oms + d;
                float n2  = pm2[h] * 0.25f * oms + 0.5f * n1;
                pm1[h] = n1; pm2[h] = n2;
                sm[SM_SKB + a_c * 196 + a_by * 14 + 2 * a_p + h] = (n2 > 0.3f) ? 1.f : 0.f;
            }
        }
        __syncthreads();

        // ---- B1: conv2 partials, thread=(oc,ic,oy-pair): 20 outputs ----
        if (tid < 480) {
            const float* wr = sm + SM_W2 + (c2_oc * 6 + c2_ic) * 25;
            const float* ib = sm + SM_SKB + c2_ic * 196;
            float acc[20];
#pragma unroll
            for (int q = 0; q < 20; q++) acc[q] = 0.f;
#pragma unroll
            for (int r = 0; r < 6; r++) {
                const float2* rp = (const float2*)(ib + (2 * c2_oy2 + r) * 14);
                float in[14];
#pragma unroll
                for (int k = 0; k < 7; k++) {
                    float2 v = rp[k];
                    in[2 * k] = v.x; in[2 * k + 1] = v.y;
                }
                if (r < 5) {
#pragma unroll
                    for (int kx = 0; kx < 5; kx++) {
                        float wv = wr[r * 5 + kx];
#pragma unroll
                        for (int ox = 0; ox < 10; ox++)
                            acc[ox] = fmaf(wv, in[kx + ox], acc[ox]);
                    }
                }
                if (r >= 1) {
#pragma unroll
                    for (int kx = 0; kx < 5; kx++) {
                        float wv = wr[(r - 1) * 5 + kx];
#pragma unroll
                        for (int ox = 0; ox < 10; ox++)
                            acc[10 + ox] = fmaf(wv, in[kx + ox], acc[10 + ox]);
                    }
                }
            }
            float2* pp = (float2*)(sm + SM_PARTB + c2_ic * 1600 + c2_oc * 100 + (2 * c2_oy2) * 10);
#pragma unroll
            for (int q = 0; q < 10; q++)
                pp[q] = make_float2(acc[2 * q], acc[2 * q + 1]);
        }
        __syncthreads();

        // ---- B2: reduce ic + lif3 + pool + lif4 + per-warp spike segments ----
        bool spiked = false;
        int myk = 0;
        if (tid < 400) {
            int oc = tid / 25, rem = tid % 25, py = rem / 5, px = rem % 5;
            float s00 = 0.f, s01 = 0.f, s10 = 0.f, s11 = 0.f;
#pragma unroll
            for (int ic = 0; ic < 6; ic++) {
                const float* pb = sm + SM_PARTB + ic * 1600 + oc * 100;
                float2 va = *(const float2*)(pb + (2 * py) * 10 + 2 * px);
                float2 vb = *(const float2*)(pb + (2 * py + 1) * 10 + 2 * px);
                s00 += va.x; s01 += va.y; s10 += vb.x; s11 += vb.y;
            }
            float dr0[4] = {s00, s01, s10, s11};
            float psum = 0.f;
            int ob = oc * 100 + (2 * py) * 10 + 2 * px;
#pragma unroll
            for (int q = 0; q < 4; q++) {
                int o = ob + (q >> 1) * 10 + (q & 1);
                float2 m = *(float2*)(sm + SM_M12C + 2 * o);
                float oms = (m.y > 0.3f) ? 0.f : 1.f;
                float n1 = m.x * 0.25f * oms + dr0[q];
                float n2 = m.y * 0.25f * oms + 0.5f * n1;
                *(float2*)(sm + SM_M12C + 2 * o) = make_float2(n1, n2);
                psum += (n2 > 0.3f) ? 1.f : 0.f;
            }
            float d   = 0.25f * psum;
            float oms = (qm2 > 0.3f) ? 0.f : 1.f;
            float n1  = qm1 * 0.25f * oms + d;
            float n2  = qm2 * 0.25f * oms + 0.5f * n1;
            qm1 = n1; qm2 = n2;
            if (n2 > 0.3f) { spiked = true; myk = oc * 25 + rem; }
        }
        {
            unsigned bm = __ballot_sync(0xffffffffu, spiked);
            if (spiked) listi[wrp * 32 + __popc(bm & ((1u << lane) - 1u))] = myk;
            if (lane == 0 && wrp < 13) wcnt[wrp] = __popc(bm);
        }
        __syncthreads();

        // ---- C1: sparse conv3 gather (u64 pairs), 4-way segment split ----
        u64 cacc = 0;
        if (tid < 512 && c_o2 < 60) {
            const u64* w3p = (const u64*)g_w3t;
            for (int w = c_sp; w < 13; w += 4) {
                int n = wcnt[w];
                const int* seg = listi + w * 32;
                for (int j = 0; j < n; j++) {
                    int k = seg[j];
                    add2(cacc, __ldg(w3p + k * 60 + c_o2));
                }
            }
            if (c_sp) *(u64*)(sm + SM_PARTC + (c_sp - 1) * 120 + 2 * c_o2) = cacc;
        }
        __syncthreads();

        // ---- C2: combine + lif5 -> SKE ----
        if (tid < 60) {
            add2(cacc, *(const u64*)(sm + SM_PARTC + 2 * tid));
            add2(cacc, *(const u64*)(sm + SM_PARTC + 120 + 2 * tid));
            add2(cacc, *(const u64*)(sm + SM_PARTC + 240 + 2 * tid));
            float2 v = u2f(cacc);
            float oms = (em2a > 0.3f) ? 0.f : 1.f;
            float n1  = em1a * 0.25f * oms + v.x;
            float n2  = em2a * 0.25f * oms + 0.5f * n1;
            em1a = n1; em2a = n2;
            sm[SM_SKE + 2 * tid] = (n2 > 0.3f) ? 1.f : 0.f;
            float omsb = (em2b > 0.3f) ? 0.f : 1.f;
            float n1b  = em1b * 0.25f * omsb + v.y;
            float n2b  = em2b * 0.25f * omsb + 0.5f * n1b;
            em1b = n1b; em2b = n2b;
            sm[SM_SKE + 2 * tid + 1] = (n2b > 0.3f) ? 1.f : 0.f;
        }
        __syncthreads();

        // ---- D: fc1 + lif6 -> SKF ----
        if (tid < 672) {
            const float* wp = sm + SM_FW1 + d_g * 120;
            float s = 0.f;
#pragma unroll
            for (int k = d_j; k < 120; k += 8) s = fmaf(wp[k], sm[SM_SKE + k], s);
            s += __shfl_xor_sync(0xffffffffu, s, 4);
            s += __shfl_xor_sync(0xffffffffu, s, 2);
            s += __shfl_xor_sync(0xffffffffu, s, 1);
            if (d_j == 0) {
                float2 m = *(float2*)(sm + SM_M12F + 2 * d_g);
                float oms = (m.y > 0.3f) ? 0.f : 1.f;
                float n1 = m.x * 0.25f * oms + s;
                float n2 = m.y * 0.25f * oms + 0.5f * n1;
                *(float2*)(sm + SM_M12F + 2 * d_g) = make_float2(n1, n2);
                sm[SM_SKF + d_g] = (n2 > 0.3f) ? 1.f : 0.f;
            }
        }
        __syncthreads();

        // ---- E: fc2 + lif7 + acc (warps 0-9) | XF(t+1) preload (warps 10+) ----
        if (wrp < 10) {
            const float* wp = sm + SM_FW2 + wrp * 84;
            float s = 0.f;
            for (int k = lane; k < 84; k += 32) s = fmaf(wp[k], sm[SM_SKF + k], s);
#pragma unroll
            for (int d2 = 16; d2 > 0; d2 >>= 1) s += __shfl_xor_sync(0xffffffffu, s, d2);
            if (lane == 0) {
                float2 m = *(float2*)(sm + SM_M12G + 2 * wrp);
                float oms = (m.y > 0.3f) ? 0.f : 1.f;
                float n1 = m.x * 0.25f * oms + s;
                float n2 = m.y * 0.25f * oms + 0.5f * n1;
                *(float2*)(sm + SM_M12G + 2 * wrp) = make_float2(n1, n2);
                sm[SM_ACC + wrp] += (n2 > 0.3f) ? 1.f : 0.f;
            }
        } else if (t + 1 < T_STEPS) {
            const unsigned* sb = spk_base + (unsigned)(t + 1) * 1024u;
            for (int i = tid - 320; i < 1024; i += 704) {
                unsigned w = __ldg(sb + (i >> 5));
                sm[SM_XF + i] = (float)((w >> (i & 31)) & 1u);
            }
        }
        __syncthreads();
    }

    if (tid < 10)
        out[b * 10 + tid] = sm[SM_ACC + tid] * (1.0f / 512.0f);
}

extern "C" void kernel_launch(void* const* d_in, const int* in_sizes, int n_in,
                              void* d_out, int out_size)
{
    const float* image = (const float*)d_in[0];
    const float* w1    = (const float*)d_in[1];
    const float* w2    = (const float*)d_in[2];
    const float* w3    = (const float*)d_in[3];
    const float* fw1   = (const float*)d_in[4];
    const float* fw2   = (const float*)d_in[5];
    float* out = (float*)d_out;

    keys_kernel<<<1, 512>>>();
    spikes_kernel<<<(T_STEPS * 32768) / 256, 256>>>(image);
    w3t_kernel<<<(48000 + 255) / 256, 256>>>(w3);
    cudaFuncSetAttribute(sim_kernel, cudaFuncAttributeMaxDynamicSharedMemorySize, SMEM_BYTES);
    sim_kernel<<<32, 1024, SMEM_BYTES>>>(w1, w2, fw1, fw2, out);
}

// round 6
// speedup vs baseline: 1.7577x; 1.0001x over previous
#include <cuda_runtime.h>
#include <cstdint>

#define T_STEPS 512

__device__ uint2    g_keys[T_STEPS];
__device__ unsigned g_spk[T_STEPS * 1024];      // [t][b*32 + word]
__device__ __align__(8) float g_w3t[400 * 120]; // transposed conv3 weights [k][o]

// ---------------- threefry2x32 (JAX), 20 rounds ----------------
__device__ __forceinline__ void threefry(unsigned k0, unsigned k1,
                                         unsigned x0, unsigned x1,
                                         unsigned &o0, unsigned &o1)
{
    unsigned k2 = k0 ^ k1 ^ 0x1BD11BDAu;
    x0 += k0; x1 += k1;
#define TF_R(r) { x0 += x1; x1 = __funnelshift_l(x1, x1, (r)); x1 ^= x0; }
    TF_R(13) TF_R(15) TF_R(26) TF_R(6)
    x0 += k1; x1 += k2 + 1u;
    TF_R(17) TF_R(29) TF_R(16) TF_R(24)
    x0 += k2; x1 += k0 + 2u;
    TF_R(13) TF_R(15) TF_R(26) TF_R(6)
    x0 += k0; x1 += k1 + 3u;
    TF_R(17) TF_R(29) TF_R(16) TF_R(24)
    x0 += k1; x1 += k2 + 4u;
    TF_R(13) TF_R(15) TF_R(26) TF_R(6)
    x0 += k2; x1 += k0 + 5u;
#undef TF_R
    o0 = x0; o1 = x1;
}

__global__ void keys_kernel()
{
    int t = threadIdx.x;
    if (t < T_STEPS) {
        unsigned a, b;
        threefry(0u, 1u, 0u, (unsigned)t, a, b);
        g_keys[t] = make_uint2(a, b);
    }
}

__global__ void __launch_bounds__(256) spikes_kernel(const float* __restrict__ image)
{
    unsigned gid = blockIdx.x * 256u + threadIdx.x;
    unsigned t = gid >> 15;
    unsigned i = gid & 32767u;
    uint2 k = g_keys[t];
    unsigned o0, o1;
    threefry(k.x, k.y, 0u, i, o0, o1);
    unsigned bits = o0 ^ o1;
    float u = __uint_as_float(0x3f800000u | (bits >> 9)) - 1.0f;
    float r = __ldg(image + i) * 0.1953125f;
    unsigned word = __ballot_sync(0xffffffffu, r > u);
    if ((threadIdx.x & 31u) == 0u)
        g_spk[t * 1024u + (i >> 5)] = word;
}

__global__ void __launch_bounds__(256) w3t_kernel(const float* __restrict__ w3)
{
    int i = blockIdx.x * 256 + threadIdx.x;   // 48000
    if (i < 48000) {
        int k = i / 120, o = i % 120;
        g_w3t[i] = w3[o * 400 + k];
    }
}

typedef unsigned long long u64;
__device__ __forceinline__ void add2(u64 &acc, u64 p)
{
    asm("add.rn.f32x2 %0, %1, %2;" : "=l"(acc) : "l"(p), "l"(acc));
}
__device__ __forceinline__ float2 u2f(u64 v)
{
    float2 r;
    asm("mov.b64 {%0, %1}, %2;" : "=f"(r.x), "=f"(r.y) : "l"(v));
    return r;
}

// ---------------- shared memory map (float offsets) ----------------
#define SM_XF     0        // 1024
#define SM_SKB    1024     // 1176
#define SM_M12A   2200     // 9408
#define SM_M12C   11608    // 3200
#define SM_PARTB  14808    // 9600 = ic(6) x oc(16) x 10 x 10
#define SM_PARTC  24408    // 360
#define SM_SKE    24768    // 120
#define SM_M12F   24888    // 168
#define SM_SKF    25056    // 84
#define SM_M12G   25140    // 20
#define SM_ACC    25160    // 10
#define SM_WCNT   25170    // 13 ints
#define SM_LIST   25184    // 416 ints
#define SM_W1     25600    // 150
#define SM_W2     25752    // 2400
#define SM_FW1    28152    // 10080
#define SM_FW2    38232    // 840
#define SM_TOTAL  39072
#define SMEM_BYTES (SM_TOTAL * 4)
#define SM_ZBEG   SM_M12A
#define SM_ZEND   SM_W1

__global__ void __launch_bounds__(1024, 1)
sim_kernel(const float* __restrict__ w1, const float* __restrict__ w2,
           const float* __restrict__ fw1, const float* __restrict__ fw2,
           float* __restrict__ out)
{
    extern __shared__ float sm[];
    int* const wcnt  = (int*)(sm + SM_WCNT);
    int* const listi = (int*)(sm + SM_LIST);

    const int tid  = threadIdx.x;
    const int b    = blockIdx.x;
    const int lane = tid & 31;
    const int wrp  = tid >> 5;

    for (int i = tid; i < 150;   i += 1024) sm[SM_W1  + i] = w1[i];
    for (int i = tid; i < 2400;  i += 1024) sm[SM_W2  + i] = w2[i];
    for (int i = tid; i < 10080; i += 1024) sm[SM_FW1 + i] = fw1[i];
    for (int i = tid; i < 840;   i += 1024) sm[SM_FW2 + i] = fw2[i];
    for (int i = tid; i < (SM_ZEND - SM_ZBEG); i += 1024) sm[SM_ZBEG + i] = 0.0f;

    const unsigned* spk_base = g_spk + b * 32;
    {   // preload XF for t=0
        unsigned w = __ldg(spk_base + wrp);
        sm[SM_XF + tid] = (float)((w >> lane) & 1u);
    }
    __syncthreads();

    // ---- static mappings ----
    const int a_c  = tid / 98;                 // A: tid<588 (c, by, p)
    const int a_r  = tid % 98;
    const int a_by = a_r / 7;
    const int a_p  = a_r % 7;
    const int c2_oc  = tid / 30;               // B1: tid<480 (oc, ic, oy2)
    const int c2_rm  = tid % 30;
    const int c2_ic  = c2_rm / 5;
    const int c2_oy2 = c2_rm % 5;
    const int c_sp = tid >> 7;                 // C1: tid<512, o2<60
    const int c_o2 = tid & 127;
    const int d_g  = tid >> 3;                 // D: tid<672
    const int d_j  = tid & 7;

    // register-resident LIF state
    float pm1[2] = {0.f, 0.f}, pm2[2] = {0.f, 0.f};   // layer2 pooled
    float qm1 = 0.f, qm2 = 0.f;                        // layer4 pooled
    float em1a = 0.f, em2a = 0.f, em1b = 0.f, em2b = 0.f; // layer5

#pragma unroll 1
    for (int t = 0; t < T_STEPS; t++) {
        // ---- A: conv1 (2x4 block, rolling rows) + lif1 + pool + lif2 ----
        if (tid < 588) {
            const float* wr = sm + SM_W1 + a_c * 25;
            float acc[8];
#pragma unroll
            for (int q = 0; q < 8; q++) acc[q] = 0.f;
#pragma unroll
            for (int r = 0; r < 6; r++) {
                const float* row = sm + SM_XF + (2 * a_by + r) * 32 + 4 * a_p;
                float4 v0 = *(const float4*)row;
                float4 v1 = *(const float4*)(row + 4);
                float in[8] = {v0.x, v0.y, v0.z, v0.w, v1.x, v1.y, v1.z, v1.w};
                if (r < 5) {
#pragma unroll
                    for (int kx = 0; kx < 5; kx++) {
                        float wv = wr[r * 5 + kx];
#pragma unroll
                        for (int j = 0; j < 4; j++)
                            acc[j] = fmaf(wv, in[kx + j], acc[j]);
                    }
                }
                if (r >= 1) {
#pragma unroll
                    for (int kx = 0; kx < 5; kx++) {
                        float wv = wr[(r - 1) * 5 + kx];
#pragma unroll
                        for (int j = 0; j < 4; j++)
                            acc[4 + j] = fmaf(wv, in[kx + j], acc[4 + j]);
                    }
                }
            }
            int ob = a_c * 784 + (2 * a_by) * 28 + 4 * a_p;
            float ps[2] = {0.f, 0.f};
#pragma unroll
            for (int q = 0; q < 8; q++) {
                int oy = q >> 2, j = q & 3;
                int o = ob + oy * 28 + j;
                float2 m = *(float2*)(sm + SM_M12A + 2 * o);
                float oms = (m.y > 0.3f) ? 0.f : 1.f;
                float n1 = m.x * 0.25f * oms + acc[q];
                float n2 = m.y * 0.25f * oms + 0.5f * n1;
                *(float2*)(sm + SM_M12A + 2 * o) = make_float2(n1, n2);
                ps[j >> 1] += (n2 > 0.3f) ? 1.f : 0.f;
            }
#pragma unroll
            for (int h = 0; h < 2; h++) {
                float d   = 0.25f * ps[h];
                float oms = (pm2[h] > 0.3f) ? 0.f : 1.f;
                float n1  = pm1[h] * 0.25f * oms + d;
                float n2  = pm2[h] * 0.25f * oms + 0.5f * n1;
                pm1[h] = n1; pm2[h] = n2;
                sm[SM_SKB + a_c * 196 + a_by * 14 + 2 * a_p + h] = (n2 > 0.3f) ? 1.f : 0.f;
            }
        }
        __syncthreads();

        // ---- B1: conv2 partials, thread=(oc,ic,oy-pair): 20 outputs ----
        if (tid < 480) {
            const float* wr = sm + SM_W2 + (c2_oc * 6 + c2_ic) * 25;
            const float* ib = sm + SM_SKB + c2_ic * 196;
            float acc[20];
#pragma unroll
            for (int q = 0; q < 20; q++) acc[q] = 0.f;
#pragma unroll
            for (int r = 0; r < 6; r++) {
                const float2* rp = (const float2*)(ib + (2 * c2_oy2 + r) * 14);
                float in[14];
#pragma unroll
                for (int k = 0; k < 7; k++) {
                    float2 v = rp[k];
                    in[2 * k] = v.x; in[2 * k + 1] = v.y;
                }
                if (r < 5) {
#pragma unroll
                    for (int kx = 0; kx < 5; kx++) {
                        float wv = wr[r * 5 + kx];
#pragma unroll
                        for (int ox = 0; ox < 10; ox++)
                            acc[ox] = fmaf(wv, in[kx + ox], acc[ox]);
                    }
                }
                if (r >= 1) {
#pragma unroll
                    for (int kx = 0; kx < 5; kx++) {
                        float wv = wr[(r - 1) * 5 + kx];
#pragma unroll
                        for (int ox = 0; ox < 10; ox++)
                            acc[10 + ox] = fmaf(wv, in[kx + ox], acc[10 + ox]);
                    }
                }
            }
            float2* pp = (float2*)(sm + SM_PARTB + c2_ic * 1600 + c2_oc * 100 + (2 * c2_oy2) * 10);
#pragma unroll
            for (int q = 0; q < 10; q++)
                pp[q] = make_float2(acc[2 * q], acc[2 * q + 1]);
        }
        __syncthreads();

        // ---- B2: reduce ic + lif3 + pool + lif4 + per-warp spike segments ----
        bool spiked = false;
        int myk = 0;
        if (tid < 400) {
            int oc = tid / 25, rem = tid % 25, py = rem / 5, px = rem % 5;
            float s00 = 0.f, s01 = 0.f, s10 = 0.f, s11 = 0.f;
#pragma unroll
            for (int ic = 0; ic < 6; ic++) {
                const float* pb = sm + SM_PARTB + ic * 1600 + oc * 100;
                float2 va = *(const float2*)(pb + (2 * py) * 10 + 2 * px);
                float2 vb = *(const float2*)(pb + (2 * py + 1) * 10 + 2 * px);
                s00 += va.x; s01 += va.y; s10 += vb.x; s11 += vb.y;
            }
            float dr0[4] = {s00, s01, s10, s11};
            float psum = 0.f;
            int ob = oc * 100 + (2 * py) * 10 + 2 * px;
#pragma unroll
            for (int q = 0; q < 4; q++) {
                int o = ob + (q >> 1) * 10 + (q & 1);
                float2 m = *(float2*)(sm + SM_M12C + 2 * o);
                float oms = (m.y > 0.3f) ? 0.f : 1.f;
                float n1 = m.x * 0.25f * oms + dr0[q];
                float n2 = m.y * 0.25f * oms + 0.5f * n1;
                *(float2*)(sm + SM_M12C + 2 * o) = make_float2(n1, n2);
                psum += (n2 > 0.3f) ? 1.f : 0.f;
            }
            float d   = 0.25f * psum;
            float oms = (qm2 > 0.3f) ? 0.f : 1.f;
            float n1  = qm1 * 0.25f * oms + d;
            float n2  = qm2 * 0.25f * oms + 0.5f * n1;
            qm1 = n1; qm2 = n2;
            if (n2 > 0.3f) { spiked = true; myk = oc * 25 + rem; }
        }
        {
            unsigned bm = __ballot_sync(0xffffffffu, spiked);
            if (spiked) listi[wrp * 32 + __popc(bm & ((1u << lane) - 1u))] = myk;
            if (lane == 0 && wrp < 13) wcnt[wrp] = __popc(bm);
        }
        __syncthreads();

        // ---- C1: sparse conv3 gather (u64 pairs), 4-way segment split ----
        u64 cacc = 0;
        if (tid < 512 && c_o2 < 60) {
            const u64* w3p = (const u64*)g_w3t;
            for (int w = c_sp; w < 13; w += 4) {
                int n = wcnt[w];
                const int* seg = listi + w * 32;
                for (int j = 0; j < n; j++) {
                    int k = seg[j];
                    add2(cacc, __ldg(w3p + k * 60 + c_o2));
                }
            }
            if (c_sp) *(u64*)(sm + SM_PARTC + (c_sp - 1) * 120 + 2 * c_o2) = cacc;
        }
        __syncthreads();

        // ---- C2: combine + lif5 -> SKE ----
        if (tid < 60) {
            add2(cacc, *(const u64*)(sm + SM_PARTC + 2 * tid));
            add2(cacc, *(const u64*)(sm + SM_PARTC + 120 + 2 * tid));
            add2(cacc, *(const u64*)(sm + SM_PARTC + 240 + 2 * tid));
            float2 v = u2f(cacc);
            float oms = (em2a > 0.3f) ? 0.f : 1.f;
            float n1  = em1a * 0.25f * oms + v.x;
            float n2  = em2a * 0.25f * oms + 0.5f * n1;
            em1a = n1; em2a = n2;
            sm[SM_SKE + 2 * tid] = (n2 > 0.3f) ? 1.f : 0.f;
            float omsb = (em2b > 0.3f) ? 0.f : 1.f;
            float n1b  = em1b * 0.25f * omsb + v.y;
            float n2b  = em2b * 0.25f * omsb + 0.5f * n1b;
            em1b = n1b; em2b = n2b;
            sm[SM_SKE + 2 * tid + 1] = (n2b > 0.3f) ? 1.f : 0.f;
        }
        __syncthreads();

        // ---- D: fc1 + lif6 -> SKF ----
        if (tid < 672) {
            const float* wp = sm + SM_FW1 + d_g * 120;
            float s = 0.f;
#pragma unroll
            for (int k = d_j; k < 120; k += 8) s = fmaf(wp[k], sm[SM_SKE + k], s);
            s += __shfl_xor_sync(0xffffffffu, s, 4);
            s += __shfl_xor_sync(0xffffffffu, s, 2);
            s += __shfl_xor_sync(0xffffffffu, s, 1);
            if (d_j == 0) {
                float2 m = *(float2*)(sm + SM_M12F + 2 * d_g);
                float oms = (m.y > 0.3f) ? 0.f : 1.f;
                float n1 = m.x * 0.25f * oms + s;
                float n2 = m.y * 0.25f * oms + 0.5f * n1;
                *(float2*)(sm + SM_M12F + 2 * d_g) = make_float2(n1, n2);
                sm[SM_SKF + d_g] = (n2 > 0.3f) ? 1.f : 0.f;
            }
        }
        __syncthreads();

        // ---- E: fc2 + lif7 + acc (warps 0-9) | XF(t+1) preload (warps 10+) ----
        if (wrp < 10) {
            const float* wp = sm + SM_FW2 + wrp * 84;
            float s = 0.f;
            for (int k = lane; k < 84; k += 32) s = fmaf(wp[k], sm[SM_SKF + k], s);
#pragma unroll
            for (int d2 = 16; d2 > 0; d2 >>= 1) s += __shfl_xor_sync(0xffffffffu, s, d2);
            if (lane == 0) {
                float2 m = *(float2*)(sm + SM_M12G + 2 * wrp);
                float oms = (m.y > 0.3f) ? 0.f : 1.f;
                float n1 = m.x * 0.25f * oms + s;
                float n2 = m.y * 0.25f * oms + 0.5f * n1;
                *(float2*)(sm + SM_M12G + 2 * wrp) = make_float2(n1, n2);
                sm[SM_ACC + wrp] += (n2 > 0.3f) ? 1.f : 0.f;
            }
        } else if (t + 1 < T_STEPS) {
            const unsigned* sb = spk_base + (unsigned)(t + 1) * 1024u;
            for (int i = tid - 320; i < 1024; i += 704) {
                unsigned w = __ldg(sb + (i >> 5));
                sm[SM_XF + i] = (float)((w >> (i & 31)) & 1u);
            }
        }
        __syncthreads();
    }

    if (tid < 10)
        out[b * 10 + tid] = sm[SM_ACC + tid] * (1.0f / 512.0f);
}

extern "C" void kernel_launch(void* const* d_in, const int* in_sizes, int n_in,
                              void* d_out, int out_size)
{
    const float* image = (const float*)d_in[0];
    const float* w1    = (const float*)d_in[1];
    const float* w2    = (const float*)d_in[2];
    const float* w3    = (const float*)d_in[3];
    const float* fw1   = (const float*)d_in[4];
    const float* fw2   = (const float*)d_in[5];
    float* out = (float*)d_out;

    keys_kernel<<<1, 512>>>();
    spikes_kernel<<<(T_STEPS * 32768) / 256, 256>>>(image);
    w3t_kernel<<<(48000 + 255) / 256, 256>>>(w3);
    cudaFuncSetAttribute(sim_kernel, cudaFuncAttributeMaxDynamicSharedMemorySize, SMEM_BYTES);
    sim_kernel<<<32, 1024, SMEM_BYTES>>>(w1, w2, fw1, fw2, out);
}